// round 15
// baseline (speedup 1.0000x reference)
#include <cuda_runtime.h>
#include <math.h>

#define BB 128
#define TT 512
#define DD 300
#define HH 300
#define NG 1200      // 4*H
#define NGRP 16      // groups of 8 rows; one 8-CTA cluster per group
#define ROWSG 8
#define CL 8         // cluster size (portable max)
#define UPC 38       // units per CTA (8*38 = 304 >= 300)
#define KC2 38       // k per chunk
#define KSTW 42      // chunk stride in floats (banks 10*kc mod 32 distinct)
#define HROW (8*KSTW)   // 336 floats per h row
#define HBUF (ROWSG*HROW)          // floats per parity
#define NCTAS (NGRP*CL) // 128 CTAs

typedef unsigned long long u64;

// ---- packed f32x2 helpers (FFMA2: only reachable via PTX) ----
__device__ __forceinline__ u64 f2pack(float lo, float hi) {
    u64 d; asm("mov.b64 %0, {%1, %2};" : "=l"(d) : "f"(lo), "f"(hi)); return d;
}
__device__ __forceinline__ void f2unpack(u64 v, float& lo, float& hi) {
    asm("mov.b64 {%0, %1}, %2;" : "=f"(lo), "=f"(hi) : "l"(v));
}
__device__ __forceinline__ u64 f2fma(u64 a, u64 b, u64 c) {
    u64 d; asm("fma.rn.f32x2 %0, %1, %2, %3;" : "=l"(d) : "l"(a), "l"(b), "l"(c)); return d;
}

__device__ __forceinline__ unsigned smem_u32(const void* p) {
    unsigned a;
    asm("{ .reg .u64 t; cvta.to.shared.u64 t, %1; cvt.u32.u64 %0, t; }" : "=r"(a) : "l"(p));
    return a;
}

// ---- device scratch ----
__device__ float g_h[2][BB*HH];          // final-h handoff (parity len&1)
__device__ float g_xz[(size_t)BB*TT*NG]; // precomputed x@Wx + b_lstm
__device__ int   g_perm[BB];             // row assignment (see init_kernel)

// ---------------------------------------------------------------------------
// init: zero h buffers; block 0 computes the row->cluster assignment.
// ROUND-ROBIN BY LENGTH RANK: rank r -> cluster r%16, slot r/16.
// Every cluster gets one row per length-quantile -> per-cluster row-step
// totals are balanced (~Sum(len)/16 each) instead of concentrating all the
// long rows in cluster 0 (which pinned the critical path at 8 rows x 512
// steps). Slot index still descends in length within each cluster, so the
// active-prefix invariant (rows with t < len form a prefix) is preserved.
// ---------------------------------------------------------------------------
__global__ void init_kernel(const int* __restrict__ lengths) {
    int i = blockIdx.x * blockDim.x + threadIdx.x;
    if (i < BB*HH) { g_h[0][i] = 0.f; g_h[1][i] = 0.f; }
    __shared__ int sle[BB];
    if (blockIdx.x == 0) {
        if (threadIdx.x < BB) sle[threadIdx.x] = lengths[threadIdx.x];
        __syncthreads();
        if (threadIdx.x < BB) {
            int t  = threadIdx.x;
            int me = sle[t];
            int rank = 0;
            for (int j = 0; j < BB; j++)
                rank += (sle[j] > me) || (sle[j] == me && j < t);
            int c = rank % NGRP;            // cluster
            int s = rank / NGRP;            // slot within cluster (len desc)
            g_perm[c*ROWSG + s] = t;
        }
    }
}

// ---------------------------------------------------------------------------
// precompute (FFMA2 version, unchanged from passing rounds 7-14)
// ---------------------------------------------------------------------------
__global__ __launch_bounds__(256) void precompute_kernel(
    const int*   __restrict__ ids,
    const int*   __restrict__ lengths,
    const float* __restrict__ emb,
    const float* __restrict__ W,
    const float* __restrict__ bl)
{
    const int b  = blockIdx.z;
    const int t0 = blockIdx.y * 128;
    const int n0 = blockIdx.x * 64;
    if (lengths[b] <= t0) return;

    __shared__ float As[16][128];
    __shared__ float Bs[16][64];
    __shared__ int   toks[128];

    const int tid = threadIdx.x;
    if (tid < 128) toks[tid] = ids[b*TT + t0 + tid];

    const int tx = tid & 15;
    const int ty = tid >> 4;
    u64 acc2[4][4];
    #pragma unroll
    for (int i = 0; i < 4; i++)
        #pragma unroll
        for (int j = 0; j < 4; j++) acc2[i][j] = 0ull;

    for (int k0 = 0; k0 < 300; k0 += 16) {
        __syncthreads();
        for (int l = tid; l < 512; l += 256) {
            int r  = l >> 2;
            int kq = l & 3;
            int k  = k0 + kq * 4;
            float4 v = make_float4(0.f, 0.f, 0.f, 0.f);
            if (k < 300) v = *(const float4*)(emb + (size_t)toks[r]*DD + k);
            As[kq*4+0][r] = v.x;
            As[kq*4+1][r] = v.y;
            As[kq*4+2][r] = v.z;
            As[kq*4+3][r] = v.w;
        }
        {
            int l  = tid;
            int kk = l >> 4;
            int q  = l & 15;
            int k  = k0 + kk;
            int n  = n0 + q * 4;
            float4 v = make_float4(0.f, 0.f, 0.f, 0.f);
            if (k < 300 && n < NG) v = *(const float4*)(W + (size_t)k*NG + n);
            *(float4*)&Bs[kk][q*4] = v;
        }
        __syncthreads();
        #pragma unroll
        for (int kk = 0; kk < 16; kk++) {
            float4 bv = *(const float4*)&Bs[kk][tx*4];
            u64 b0 = f2pack(bv.x, bv.x);
            u64 b1 = f2pack(bv.y, bv.y);
            u64 b2 = f2pack(bv.z, bv.z);
            u64 b3 = f2pack(bv.w, bv.w);
            const u64* a2 = (const u64*)&As[kk][ty*8];
            #pragma unroll
            for (int mp = 0; mp < 4; mp++) {
                u64 av = a2[mp];
                acc2[mp][0] = f2fma(av, b0, acc2[mp][0]);
                acc2[mp][1] = f2fma(av, b1, acc2[mp][1]);
                acc2[mp][2] = f2fma(av, b2, acc2[mp][2]);
                acc2[mp][3] = f2fma(av, b3, acc2[mp][3]);
            }
        }
    }

    const int n = n0 + tx * 4;
    if (n < NG) {
        float4 blv = *(const float4*)(bl + n);
        #pragma unroll
        for (int mp = 0; mp < 4; mp++) {
            float x0,x1,y0,y1,z0,z1,q0,q1;
            f2unpack(acc2[mp][0], x0, x1);
            f2unpack(acc2[mp][1], y0, y1);
            f2unpack(acc2[mp][2], z0, z1);
            f2unpack(acc2[mp][3], q0, q1);
            int t = t0 + ty*8 + 2*mp;
            float4 o0 = make_float4(x0+blv.x, y0+blv.y, z0+blv.z, q0+blv.w);
            float4 o1 = make_float4(x1+blv.x, y1+blv.y, z1+blv.z, q1+blv.w);
            *(float4*)(g_xz + ((size_t)b*TT + t  )*NG + n) = o0;
            *(float4*)(g_xz + ((size_t)b*TT + t+1)*NG + n) = o1;
        }
    }
}

// ---------------------------------------------------------------------------
// persistent recurrence v9 (passing r13/r14 skeleton): 8-CTA cluster + DSMEM
// push, split arrive/wait with xz prefetch between, row-pair matmul,
// g_h written once per row at t == len-1 (parity len&1).
// ---------------------------------------------------------------------------
__global__ __launch_bounds__(256, 1) __cluster_dims__(CL, 1, 1)
void lstm_persistent(
    const float* __restrict__ W,
    const int*   __restrict__ lengths)
{
    __shared__ __align__(16) float hsm[2][HBUF];   // 2 x 8 x 336
    __shared__ __align__(16) float zsm[ROWSG*160]; // 8 rows x 40 slots x 4 gates
    __shared__ int sli[ROWSG], spr[ROWSG];

    const int tid   = threadIdx.x;
    const int wid   = tid >> 5;
    const int lane  = tid & 31;
    const int kc    = lane >> 2;          // k-chunk 0..7
    const int gg    = lane & 3;           // gate
    const int gid   = blockIdx.x / CL;
    const int crank = blockIdx.x % CL;

    if (tid < ROWSG) {
        int pr = g_perm[gid*ROWSG + tid];
        spr[tid] = pr;
        sli[tid] = lengths[pr];
    }
    // zero both hsm parities (pad slots stay 0 forever)
    {
        float4 z4 = make_float4(0.f, 0.f, 0.f, 0.f);
        float4* p4 = (float4*)&hsm[0][0];
        for (int l = tid; l < 2*HBUF/4; l += 256) p4[l] = z4;
    }

    // W -> registers: 5 unit-slots x 19 f32x2 (this thread's k-chunk, gate)
    u64 w2[5][19];
    #pragma unroll
    for (int jj = 0; jj < 5; jj++) {
        int  ul = wid*5 + jj;
        int  ug = crank*UPC + ul;
        bool uv = (ul < UPC) && (ug < HH);
        int  col = gg*HH + (uv ? ug : 0);
        #pragma unroll
        for (int i = 0; i < 19; i++) {
            int k0 = kc*KC2 + 2*i;
            float lo = (uv && k0     < HH) ? W[(size_t)(HH + k0    )*NG + col] : 0.f;
            float hi = (uv && k0 + 1 < HH) ? W[(size_t)(HH + k0 + 1)*NG + col] : 0.f;
            w2[jj][i] = f2pack(lo, hi);
        }
    }
    __syncthreads();
    int slr[ROWSG];
    #pragma unroll
    for (int i = 0; i < ROWSG; i++) slr[i] = sli[i];
    const int maxlen = slr[0];

    // epilogue mapping: tid<152 owns (row m, unit pair ul2, ul2+1)
    const bool e_has = (tid < ROWSG*19);
    const int  e_m   = e_has ? tid/19 : 0;
    const int  e_jp  = e_has ? tid - e_m*19 : 0;
    const int  e_ul  = 2*e_jp;
    const int  e_ug  = crank*UPC + e_ul;
    const bool e_val = e_has && (e_ug < HH);   // pairs fully valid/invalid
    const int  e_b   = spr[e_m];
    const int  e_len = e_has ? slr[e_m] : 0;
    const unsigned e_offb = (unsigned)((e_m*HROW + crank*KSTW + e_ul) * 4);
    const float* e_xbase = g_xz + (size_t)e_b*TT*NG + (e_val ? e_ug : 0);

    // mapa'd peer base addresses for hsm[0]
    unsigned rbase[CL];
    {
        unsigned locb = smem_u32(&hsm[0][0]);
        #pragma unroll
        for (int r = 0; r < CL; r++)
            asm("mapa.shared::cluster.u32 %0, %1, %2;"
                : "=r"(rbase[r]) : "r"(locb), "r"(r));
    }

    // all CTAs' hsm zero before any pushes can land
    asm volatile("barrier.cluster.arrive.aligned;" ::: "memory");
    asm volatile("barrier.cluster.wait.aligned;"   ::: "memory");

    float c0 = 0.f, c1 = 0.f;

    // prefetch xz for t = 0
    float pf[4][2];
    {
        const bool a0 = e_val && (0 < e_len);
        const float* xp = e_xbase;
        #pragma unroll
        for (int g = 0; g < 4; g++) {
            pf[g][0] = a0 ? __ldcg(xp + g*HH    ) : 0.f;
            pf[g][1] = a0 ? __ldcg(xp + g*HH + 1) : 0.f;
        }
    }

    for (int t = 0; t < maxlen; t++) {
        const int p = t & 1;
        const unsigned poff = (unsigned)(p ^ 1) * (unsigned)(HBUF * 4);
        int nact = 0;
        #pragma unroll
        for (int i = 0; i < ROWSG; i++) nact += (slr[i] > t);
        const bool act = e_val && (t < e_len);

        // ---- matmul over active rows, 2 rows in flight ----
        const float* hp = &hsm[p][0];
        int m = 0;
        for (; m + 2 <= nact; m += 2) {
            const u64* hA = (const u64*)(hp + (m  )*HROW + kc*KSTW);
            const u64* hB = (const u64*)(hp + (m+1)*HROW + kc*KSTW);
            u64 A0=0ull,A1=0ull,A2=0ull,A3=0ull,A4=0ull;
            u64 B0=0ull,B1=0ull,B2=0ull,B3=0ull,B4=0ull;
            #pragma unroll
            for (int i = 0; i < 19; i++) {
                u64 ha = hA[i];
                u64 hb = hB[i];
                A0 = f2fma(w2[0][i], ha, A0);  B0 = f2fma(w2[0][i], hb, B0);
                A1 = f2fma(w2[1][i], ha, A1);  B1 = f2fma(w2[1][i], hb, B1);
                A2 = f2fma(w2[2][i], ha, A2);  B2 = f2fma(w2[2][i], hb, B2);
                A3 = f2fma(w2[3][i], ha, A3);  B3 = f2fma(w2[3][i], hb, B3);
                A4 = f2fma(w2[4][i], ha, A4);  B4 = f2fma(w2[4][i], hb, B4);
            }
            float a0,a1,a2,a3,a4,b0,b1,b2,b3,b4,lo,hi;
            f2unpack(A0,lo,hi); a0 = lo+hi;
            f2unpack(B0,lo,hi); b0 = lo+hi;
            f2unpack(A1,lo,hi); a1 = lo+hi;
            f2unpack(B1,lo,hi); b1 = lo+hi;
            f2unpack(A2,lo,hi); a2 = lo+hi;
            f2unpack(B2,lo,hi); b2 = lo+hi;
            f2unpack(A3,lo,hi); a3 = lo+hi;
            f2unpack(B3,lo,hi); b3 = lo+hi;
            f2unpack(A4,lo,hi); a4 = lo+hi;
            f2unpack(B4,lo,hi); b4 = lo+hi;
            #pragma unroll
            for (int o = 4; o <= 16; o <<= 1) {
                a0 += __shfl_xor_sync(0xffffffffu, a0, o);
                b0 += __shfl_xor_sync(0xffffffffu, b0, o);
                a1 += __shfl_xor_sync(0xffffffffu, a1, o);
                b1 += __shfl_xor_sync(0xffffffffu, b1, o);
                a2 += __shfl_xor_sync(0xffffffffu, a2, o);
                b2 += __shfl_xor_sync(0xffffffffu, b2, o);
                a3 += __shfl_xor_sync(0xffffffffu, a3, o);
                b3 += __shfl_xor_sync(0xffffffffu, b3, o);
                a4 += __shfl_xor_sync(0xffffffffu, a4, o);
                b4 += __shfl_xor_sync(0xffffffffu, b4, o);
            }
            if (lane < 4) {   // kc == 0; gg = lane
                float* zA = &zsm[(m  )*160 + wid*20 + gg];
                float* zB = &zsm[(m+1)*160 + wid*20 + gg];
                zA[ 0] = a0;  zB[ 0] = b0;
                zA[ 4] = a1;  zB[ 4] = b1;
                zA[ 8] = a2;  zB[ 8] = b2;
                zA[12] = a3;  zB[12] = b3;
                zA[16] = a4;  zB[16] = b4;
            }
        }
        if (m < nact) {
            const u64* hA = (const u64*)(hp + m*HROW + kc*KSTW);
            u64 A0=0ull,A1=0ull,A2=0ull,A3=0ull,A4=0ull;
            #pragma unroll
            for (int i = 0; i < 19; i++) {
                u64 ha = hA[i];
                A0 = f2fma(w2[0][i], ha, A0);
                A1 = f2fma(w2[1][i], ha, A1);
                A2 = f2fma(w2[2][i], ha, A2);
                A3 = f2fma(w2[3][i], ha, A3);
                A4 = f2fma(w2[4][i], ha, A4);
            }
            float a0,a1,a2,a3,a4,lo,hi;
            f2unpack(A0,lo,hi); a0 = lo+hi;
            f2unpack(A1,lo,hi); a1 = lo+hi;
            f2unpack(A2,lo,hi); a2 = lo+hi;
            f2unpack(A3,lo,hi); a3 = lo+hi;
            f2unpack(A4,lo,hi); a4 = lo+hi;
            #pragma unroll
            for (int o = 4; o <= 16; o <<= 1) {
                a0 += __shfl_xor_sync(0xffffffffu, a0, o);
                a1 += __shfl_xor_sync(0xffffffffu, a1, o);
                a2 += __shfl_xor_sync(0xffffffffu, a2, o);
                a3 += __shfl_xor_sync(0xffffffffu, a3, o);
                a4 += __shfl_xor_sync(0xffffffffu, a4, o);
            }
            if (lane < 4) {
                float* zA = &zsm[m*160 + wid*20 + gg];
                zA[ 0] = a0;
                zA[ 4] = a1;
                zA[ 8] = a2;
                zA[12] = a3;
                zA[16] = a4;
            }
        }
        __syncthreads();

        // ---- epilogue: 2 units per thread; push h pair to all 8 CTAs ----
        if (act) {
            float4 za = *(const float4*)&zsm[e_m*160 + e_ul*4];
            float4 zb = *(const float4*)&zsm[e_m*160 + e_ul*4 + 4];
            // unit e_ug
            float zi = za.x + pf[0][0];
            float zj = za.y + pf[1][0];
            float zf = za.z + pf[2][0];
            float zo = za.w + pf[3][0];
            float si = 1.f / (1.f + __expf(-zi));
            float sf = 1.f / (1.f + __expf(-(zf + 1.f)));  // FORGET_BIAS=1
            float so = 1.f / (1.f + __expf(-zo));
            float tj = tanhf(zj);
            c0 = c0 * sf + si * tj;
            float h0 = tanhf(c0) * so;
            // unit e_ug+1
            zi = zb.x + pf[0][1];
            zj = zb.y + pf[1][1];
            zf = zb.z + pf[2][1];
            zo = zb.w + pf[3][1];
            si = 1.f / (1.f + __expf(-zi));
            sf = 1.f / (1.f + __expf(-(zf + 1.f)));
            so = 1.f / (1.f + __expf(-zo));
            tj = tanhf(zj);
            c1 = c1 * sf + si * tj;
            float h1 = tanhf(c1) * so;

            if (t == e_len - 1) {   // final state for this row: single handoff
                float* hwr = g_h[(t & 1) ^ 1];
                __stcg(&hwr[e_b*HH + e_ug],     h0);
                __stcg(&hwr[e_b*HH + e_ug + 1], h1);
            }

            u64 hv2 = f2pack(h0, h1);
            unsigned off = poff + e_offb;
            #pragma unroll
            for (int r = 0; r < CL; r++)
                asm volatile("st.shared::cluster.b64 [%0], %1;"
                             :: "r"(rbase[r] + off), "l"(hv2) : "memory");
        }

        // ---- split barrier: arrive, prefetch next xz, then wait ----
        asm volatile("barrier.cluster.arrive.aligned;" ::: "memory");
        {
            const bool an = e_val && (t + 1 < e_len);
            const float* xp = e_xbase + (size_t)(t + 1)*NG;
            #pragma unroll
            for (int g = 0; g < 4; g++) {
                pf[g][0] = an ? __ldcg(xp + g*HH    ) : 0.f;
                pf[g][1] = an ? __ldcg(xp + g*HH + 1) : 0.f;
            }
        }
        asm volatile("barrier.cluster.wait.aligned;" ::: "memory");
    }
}

// ---------------------------------------------------------------------------
// final: logits + mean NLL. Row b's final h lives in buffer (lengths[b] & 1).
// ---------------------------------------------------------------------------
__global__ void final_kernel(
    const float* __restrict__ Wd,
    const float* __restrict__ bd,
    const int*   __restrict__ labels,
    const int*   __restrict__ lengths,
    float*       __restrict__ out,
    int out_size)
{
    __shared__ float red[128];
    __shared__ float wd_s[900];
    int b = threadIdx.x;
    for (int i = b; i < 900; i += 128) wd_s[i] = Wd[i];
    __syncthreads();

    const float* h = g_h[lengths[b] & 1] + b*HH;

    float a0 = bd[0], a1 = bd[1], a2 = bd[2];
    #pragma unroll 5
    for (int k = 0; k < HH; k += 4) {
        float4 hv = *(const float4*)(h + k);
        a0 += hv.x*wd_s[(k+0)*3+0] + hv.y*wd_s[(k+1)*3+0]
            + hv.z*wd_s[(k+2)*3+0] + hv.w*wd_s[(k+3)*3+0];
        a1 += hv.x*wd_s[(k+0)*3+1] + hv.y*wd_s[(k+1)*3+1]
            + hv.z*wd_s[(k+2)*3+1] + hv.w*wd_s[(k+3)*3+1];
        a2 += hv.x*wd_s[(k+0)*3+2] + hv.y*wd_s[(k+1)*3+2]
            + hv.z*wd_s[(k+2)*3+2] + hv.w*wd_s[(k+3)*3+2];
    }
    float mx  = fmaxf(a0, fmaxf(a1, a2));
    float lse = mx + logf(expf(a0 - mx) + expf(a1 - mx) + expf(a2 - mx));
    int   lab = labels[b];
    float sel = (lab == 0) ? a0 : ((lab == 1) ? a1 : a2);
    float nll = lse - sel;

    int off = (out_size >= 385) ? 1 : 0;
    if (out_size >= 384) {
        out[off + b*3 + 0] = a0;
        out[off + b*3 + 1] = a1;
        out[off + b*3 + 2] = a2;
    }
    red[b] = nll;
    __syncthreads();
    for (int s = 64; s; s >>= 1) {
        if (b < s) red[b] += red[b + s];
        __syncthreads();
    }
    if (b == 0 && (off == 1 || out_size < 384)) out[0] = red[0] * (1.f / 128.f);
}

// ---------------------------------------------------------------------------
extern "C" void kernel_launch(void* const* d_in, const int* in_sizes, int n_in,
                              void* d_out, int out_size)
{
    const int*   ids     = (const int*)  d_in[0];
    const int*   lengths = (const int*)  d_in[1];
    const int*   labels  = (const int*)  d_in[2];
    const float* emb     = (const float*)d_in[3];
    const float* W       = (const float*)d_in[4];
    const float* bl      = (const float*)d_in[5];
    const float* Wd      = (const float*)d_in[6];
    const float* bd      = (const float*)d_in[7];
    float* out = (float*)d_out;

    init_kernel<<<(BB*HH + 255)/256, 256>>>(lengths);
    precompute_kernel<<<dim3(19, 4, BB), 256>>>(ids, lengths, emb, W, bl);
    lstm_persistent<<<NCTAS, 256>>>(W, lengths);
    final_kernel<<<1, 128>>>(Wd, bd, labels, lengths, out, out_size);
}

// round 16
// speedup vs baseline: 1.0863x; 1.0863x over previous
#include <cuda_runtime.h>
#include <math.h>

#define BB 128
#define TT 512
#define DD 300
#define HH 300
#define NG 1200      // 4*H
#define NGRP 16      // groups of 8 rows; one 8-CTA cluster per group
#define ROWSG 8
#define CL 8         // cluster size (portable max)
#define UPC 38       // units per CTA (8*38 = 304 >= 300)
#define KC2 38       // k per chunk
#define KSTW 42      // chunk stride in floats (banks 10*kc mod 32 distinct)
#define HROW (8*KSTW)   // 336 floats per h row
#define HBUF (ROWSG*HROW)          // floats per parity
#define NCTAS (NGRP*CL) // 128 CTAs

typedef unsigned long long u64;

// ---- packed f32x2 helpers (FFMA2: only reachable via PTX) ----
__device__ __forceinline__ u64 f2pack(float lo, float hi) {
    u64 d; asm("mov.b64 %0, {%1, %2};" : "=l"(d) : "f"(lo), "f"(hi)); return d;
}
__device__ __forceinline__ void f2unpack(u64 v, float& lo, float& hi) {
    asm("mov.b64 {%0, %1}, %2;" : "=f"(lo), "=f"(hi) : "l"(v));
}
__device__ __forceinline__ u64 f2fma(u64 a, u64 b, u64 c) {
    u64 d; asm("fma.rn.f32x2 %0, %1, %2, %3;" : "=l"(d) : "l"(a), "l"(b), "l"(c)); return d;
}

__device__ __forceinline__ unsigned smem_u32(const void* p) {
    unsigned a;
    asm("{ .reg .u64 t; cvta.to.shared.u64 t, %1; cvt.u32.u64 %0, t; }" : "=r"(a) : "l"(p));
    return a;
}

// ---- device scratch ----
__device__ float g_h[2][BB*HH];          // final-h handoff (parity len&1)
__device__ float g_xz[(size_t)BB*TT*NG]; // precomputed x@Wx + b_lstm
__device__ int   g_perm[BB];             // rows sorted by length descending

// ---------------------------------------------------------------------------
// init: zero h buffers; block 0 rank-sorts rows by length (desc) into g_perm.
// SORTED-CONTIGUOUS grouping (r13 winner; round-robin regressed in r15):
// cluster g = ranks 8g..8g+7 -> only ONE cluster runs the full 512 steps.
// ---------------------------------------------------------------------------
__global__ void init_kernel(const int* __restrict__ lengths) {
    int i = blockIdx.x * blockDim.x + threadIdx.x;
    if (i < BB*HH) { g_h[0][i] = 0.f; g_h[1][i] = 0.f; }
    __shared__ int sle[BB];
    if (blockIdx.x == 0) {
        if (threadIdx.x < BB) sle[threadIdx.x] = lengths[threadIdx.x];
        __syncthreads();
        if (threadIdx.x < BB) {
            int t  = threadIdx.x;
            int me = sle[t];
            int rank = 0;
            for (int j = 0; j < BB; j++)
                rank += (sle[j] > me) || (sle[j] == me && j < t);
            g_perm[rank] = t;
        }
    }
}

// ---------------------------------------------------------------------------
// precompute: g_xz[b][t][n] = embedding[ids[b][t]] @ W_lstm[0:300, n] + b_lstm[n]
// v2: DOUBLE-BUFFERED k-pipeline. Next k-block's gathers (A: embedding rows,
// B: W slice) are issued into registers BEFORE computing the current block;
// the dependent STS lands one iteration later, so L2 gather latency (~250-580
// cyc x 19 blocks, previously serialized by the per-block syncthreads) is
// hidden behind ~1000 cyc of FFMA2 per block. FMA order identical to r13.
// ---------------------------------------------------------------------------
__global__ __launch_bounds__(256) void precompute_kernel(
    const int*   __restrict__ ids,
    const int*   __restrict__ lengths,
    const float* __restrict__ emb,
    const float* __restrict__ W,
    const float* __restrict__ bl)
{
    const int b  = blockIdx.z;
    const int t0 = blockIdx.y * 128;
    const int n0 = blockIdx.x * 64;
    if (lengths[b] <= t0) return;

    __shared__ float As[2][16][128];
    __shared__ float Bs[2][16][64];
    __shared__ int   toks[128];

    const int tid = threadIdx.x;
    if (tid < 128) toks[tid] = ids[b*TT + t0 + tid];

    const int tx = tid & 15;
    const int ty = tid >> 4;

    // fixed per-thread load roles
    const int ar0  = tid >> 2,         akq0 = tid & 3;          // A slot 0
    const int ar1  = (tid + 256) >> 2, akq1 = (tid + 256) & 3;  // A slot 1
    const int bkk  = tid >> 4,         bq   = tid & 15;         // B slot

    u64 acc2[4][4];
    #pragma unroll
    for (int i = 0; i < 4; i++)
        #pragma unroll
        for (int j = 0; j < 4; j++) acc2[i][j] = 0ull;

    __syncthreads();   // toks visible

    // register-stage block 0
    float4 ra0, ra1, rb;
    {
        int ka = akq0 * 4;
        ra0 = *(const float4*)(emb + (size_t)toks[ar0]*DD + ka);   // <= 12 < 300
        int kb = akq1 * 4;
        ra1 = *(const float4*)(emb + (size_t)toks[ar1]*DD + kb);
        int kw = bkk;                                               // <= 15 < 300
        int n  = n0 + bq * 4;
        rb = (n < NG) ? *(const float4*)(W + (size_t)kw*NG + n)
                      : make_float4(0.f, 0.f, 0.f, 0.f);
    }

    for (int ib = 0; ib < 19; ib++) {
        const int cb = ib & 1;
        // commit staged regs to smem buffer cb
        As[cb][akq0*4+0][ar0] = ra0.x;
        As[cb][akq0*4+1][ar0] = ra0.y;
        As[cb][akq0*4+2][ar0] = ra0.z;
        As[cb][akq0*4+3][ar0] = ra0.w;
        As[cb][akq1*4+0][ar1] = ra1.x;
        As[cb][akq1*4+1][ar1] = ra1.y;
        As[cb][akq1*4+2][ar1] = ra1.z;
        As[cb][akq1*4+3][ar1] = ra1.w;
        *(float4*)&Bs[cb][bkk][bq*4] = rb;
        __syncthreads();

        // prefetch next block into regs (LDGs in flight during compute)
        if (ib < 18) {
            const int k0n = (ib + 1) * 16;
            int ka = k0n + akq0 * 4;
            ra0 = (ka < 300) ? *(const float4*)(emb + (size_t)toks[ar0]*DD + ka)
                             : make_float4(0.f, 0.f, 0.f, 0.f);
            int kb = k0n + akq1 * 4;
            ra1 = (kb < 300) ? *(const float4*)(emb + (size_t)toks[ar1]*DD + kb)
                             : make_float4(0.f, 0.f, 0.f, 0.f);
            int kw = k0n + bkk;
            int n  = n0 + bq * 4;
            rb = (kw < 300 && n < NG) ? *(const float4*)(W + (size_t)kw*NG + n)
                                      : make_float4(0.f, 0.f, 0.f, 0.f);
        }

        // compute on buffer cb
        #pragma unroll
        for (int kk = 0; kk < 16; kk++) {
            float4 bv = *(const float4*)&Bs[cb][kk][tx*4];
            u64 b0 = f2pack(bv.x, bv.x);
            u64 b1 = f2pack(bv.y, bv.y);
            u64 b2 = f2pack(bv.z, bv.z);
            u64 b3 = f2pack(bv.w, bv.w);
            const u64* a2 = (const u64*)&As[cb][kk][ty*8];
            #pragma unroll
            for (int mp = 0; mp < 4; mp++) {
                u64 av = a2[mp];
                acc2[mp][0] = f2fma(av, b0, acc2[mp][0]);
                acc2[mp][1] = f2fma(av, b1, acc2[mp][1]);
                acc2[mp][2] = f2fma(av, b2, acc2[mp][2]);
                acc2[mp][3] = f2fma(av, b3, acc2[mp][3]);
            }
        }
        __syncthreads();   // compute done before this buffer is overwritten
    }

    const int n = n0 + tx * 4;
    if (n < NG) {
        float4 blv = *(const float4*)(bl + n);
        #pragma unroll
        for (int mp = 0; mp < 4; mp++) {
            float x0,x1,y0,y1,z0,z1,q0,q1;
            f2unpack(acc2[mp][0], x0, x1);
            f2unpack(acc2[mp][1], y0, y1);
            f2unpack(acc2[mp][2], z0, z1);
            f2unpack(acc2[mp][3], q0, q1);
            int t = t0 + ty*8 + 2*mp;
            float4 o0 = make_float4(x0+blv.x, y0+blv.y, z0+blv.z, q0+blv.w);
            float4 o1 = make_float4(x1+blv.x, y1+blv.y, z1+blv.z, q1+blv.w);
            *(float4*)(g_xz + ((size_t)b*TT + t  )*NG + n) = o0;
            *(float4*)(g_xz + ((size_t)b*TT + t+1)*NG + n) = o1;
        }
    }
}

// ---------------------------------------------------------------------------
// persistent recurrence v9 (r13/r14 winner, unchanged): 8-CTA cluster + DSMEM
// push, split arrive/wait with xz prefetch between, row-pair matmul,
// g_h written once per row at t == len-1 (parity len&1).
// ---------------------------------------------------------------------------
__global__ __launch_bounds__(256, 1) __cluster_dims__(CL, 1, 1)
void lstm_persistent(
    const float* __restrict__ W,
    const int*   __restrict__ lengths)
{
    __shared__ __align__(16) float hsm[2][HBUF];   // 2 x 8 x 336
    __shared__ __align__(16) float zsm[ROWSG*160]; // 8 rows x 40 slots x 4 gates
    __shared__ int sli[ROWSG], spr[ROWSG];

    const int tid   = threadIdx.x;
    const int wid   = tid >> 5;
    const int lane  = tid & 31;
    const int kc    = lane >> 2;          // k-chunk 0..7
    const int gg    = lane & 3;           // gate
    const int gid   = blockIdx.x / CL;
    const int crank = blockIdx.x % CL;

    if (tid < ROWSG) {
        int pr = g_perm[gid*ROWSG + tid];
        spr[tid] = pr;
        sli[tid] = lengths[pr];
    }
    // zero both hsm parities (pad slots stay 0 forever)
    {
        float4 z4 = make_float4(0.f, 0.f, 0.f, 0.f);
        float4* p4 = (float4*)&hsm[0][0];
        for (int l = tid; l < 2*HBUF/4; l += 256) p4[l] = z4;
    }

    // W -> registers: 5 unit-slots x 19 f32x2 (this thread's k-chunk, gate)
    u64 w2[5][19];
    #pragma unroll
    for (int jj = 0; jj < 5; jj++) {
        int  ul = wid*5 + jj;
        int  ug = crank*UPC + ul;
        bool uv = (ul < UPC) && (ug < HH);
        int  col = gg*HH + (uv ? ug : 0);
        #pragma unroll
        for (int i = 0; i < 19; i++) {
            int k0 = kc*KC2 + 2*i;
            float lo = (uv && k0     < HH) ? W[(size_t)(HH + k0    )*NG + col] : 0.f;
            float hi = (uv && k0 + 1 < HH) ? W[(size_t)(HH + k0 + 1)*NG + col] : 0.f;
            w2[jj][i] = f2pack(lo, hi);
        }
    }
    __syncthreads();
    int slr[ROWSG];
    #pragma unroll
    for (int i = 0; i < ROWSG; i++) slr[i] = sli[i];
    const int maxlen = slr[0];

    // epilogue mapping: tid<152 owns (row m, unit pair ul2, ul2+1)
    const bool e_has = (tid < ROWSG*19);
    const int  e_m   = e_has ? tid/19 : 0;
    const int  e_jp  = e_has ? tid - e_m*19 : 0;
    const int  e_ul  = 2*e_jp;
    const int  e_ug  = crank*UPC + e_ul;
    const bool e_val = e_has && (e_ug < HH);   // pairs fully valid/invalid
    const int  e_b   = spr[e_m];
    const int  e_len = e_has ? slr[e_m] : 0;
    const unsigned e_offb = (unsigned)((e_m*HROW + crank*KSTW + e_ul) * 4);
    const float* e_xbase = g_xz + (size_t)e_b*TT*NG + (e_val ? e_ug : 0);

    // mapa'd peer base addresses for hsm[0]
    unsigned rbase[CL];
    {
        unsigned locb = smem_u32(&hsm[0][0]);
        #pragma unroll
        for (int r = 0; r < CL; r++)
            asm("mapa.shared::cluster.u32 %0, %1, %2;"
                : "=r"(rbase[r]) : "r"(locb), "r"(r));
    }

    // all CTAs' hsm zero before any pushes can land
    asm volatile("barrier.cluster.arrive.aligned;" ::: "memory");
    asm volatile("barrier.cluster.wait.aligned;"   ::: "memory");

    float c0 = 0.f, c1 = 0.f;

    // prefetch xz for t = 0
    float pf[4][2];
    {
        const bool a0 = e_val && (0 < e_len);
        const float* xp = e_xbase;
        #pragma unroll
        for (int g = 0; g < 4; g++) {
            pf[g][0] = a0 ? __ldcg(xp + g*HH    ) : 0.f;
            pf[g][1] = a0 ? __ldcg(xp + g*HH + 1) : 0.f;
        }
    }

    for (int t = 0; t < maxlen; t++) {
        const int p = t & 1;
        const unsigned poff = (unsigned)(p ^ 1) * (unsigned)(HBUF * 4);
        int nact = 0;
        #pragma unroll
        for (int i = 0; i < ROWSG; i++) nact += (slr[i] > t);
        const bool act = e_val && (t < e_len);

        // ---- matmul over active rows, 2 rows in flight ----
        const float* hp = &hsm[p][0];
        int m = 0;
        for (; m + 2 <= nact; m += 2) {
            const u64* hA = (const u64*)(hp + (m  )*HROW + kc*KSTW);
            const u64* hB = (const u64*)(hp + (m+1)*HROW + kc*KSTW);
            u64 A0=0ull,A1=0ull,A2=0ull,A3=0ull,A4=0ull;
            u64 B0=0ull,B1=0ull,B2=0ull,B3=0ull,B4=0ull;
            #pragma unroll
            for (int i = 0; i < 19; i++) {
                u64 ha = hA[i];
                u64 hb = hB[i];
                A0 = f2fma(w2[0][i], ha, A0);  B0 = f2fma(w2[0][i], hb, B0);
                A1 = f2fma(w2[1][i], ha, A1);  B1 = f2fma(w2[1][i], hb, B1);
                A2 = f2fma(w2[2][i], ha, A2);  B2 = f2fma(w2[2][i], hb, B2);
                A3 = f2fma(w2[3][i], ha, A3);  B3 = f2fma(w2[3][i], hb, B3);
                A4 = f2fma(w2[4][i], ha, A4);  B4 = f2fma(w2[4][i], hb, B4);
            }
            float a0,a1,a2,a3,a4,b0,b1,b2,b3,b4,lo,hi;
            f2unpack(A0,lo,hi); a0 = lo+hi;
            f2unpack(B0,lo,hi); b0 = lo+hi;
            f2unpack(A1,lo,hi); a1 = lo+hi;
            f2unpack(B1,lo,hi); b1 = lo+hi;
            f2unpack(A2,lo,hi); a2 = lo+hi;
            f2unpack(B2,lo,hi); b2 = lo+hi;
            f2unpack(A3,lo,hi); a3 = lo+hi;
            f2unpack(B3,lo,hi); b3 = lo+hi;
            f2unpack(A4,lo,hi); a4 = lo+hi;
            f2unpack(B4,lo,hi); b4 = lo+hi;
            #pragma unroll
            for (int o = 4; o <= 16; o <<= 1) {
                a0 += __shfl_xor_sync(0xffffffffu, a0, o);
                b0 += __shfl_xor_sync(0xffffffffu, b0, o);
                a1 += __shfl_xor_sync(0xffffffffu, a1, o);
                b1 += __shfl_xor_sync(0xffffffffu, b1, o);
                a2 += __shfl_xor_sync(0xffffffffu, a2, o);
                b2 += __shfl_xor_sync(0xffffffffu, b2, o);
                a3 += __shfl_xor_sync(0xffffffffu, a3, o);
                b3 += __shfl_xor_sync(0xffffffffu, b3, o);
                a4 += __shfl_xor_sync(0xffffffffu, a4, o);
                b4 += __shfl_xor_sync(0xffffffffu, b4, o);
            }
            if (lane < 4) {   // kc == 0; gg = lane
                float* zA = &zsm[(m  )*160 + wid*20 + gg];
                float* zB = &zsm[(m+1)*160 + wid*20 + gg];
                zA[ 0] = a0;  zB[ 0] = b0;
                zA[ 4] = a1;  zB[ 4] = b1;
                zA[ 8] = a2;  zB[ 8] = b2;
                zA[12] = a3;  zB[12] = b3;
                zA[16] = a4;  zB[16] = b4;
            }
        }
        if (m < nact) {
            const u64* hA = (const u64*)(hp + m*HROW + kc*KSTW);
            u64 A0=0ull,A1=0ull,A2=0ull,A3=0ull,A4=0ull;
            #pragma unroll
            for (int i = 0; i < 19; i++) {
                u64 ha = hA[i];
                A0 = f2fma(w2[0][i], ha, A0);
                A1 = f2fma(w2[1][i], ha, A1);
                A2 = f2fma(w2[2][i], ha, A2);
                A3 = f2fma(w2[3][i], ha, A3);
                A4 = f2fma(w2[4][i], ha, A4);
            }
            float a0,a1,a2,a3,a4,lo,hi;
            f2unpack(A0,lo,hi); a0 = lo+hi;
            f2unpack(A1,lo,hi); a1 = lo+hi;
            f2unpack(A2,lo,hi); a2 = lo+hi;
            f2unpack(A3,lo,hi); a3 = lo+hi;
            f2unpack(A4,lo,hi); a4 = lo+hi;
            #pragma unroll
            for (int o = 4; o <= 16; o <<= 1) {
                a0 += __shfl_xor_sync(0xffffffffu, a0, o);
                a1 += __shfl_xor_sync(0xffffffffu, a1, o);
                a2 += __shfl_xor_sync(0xffffffffu, a2, o);
                a3 += __shfl_xor_sync(0xffffffffu, a3, o);
                a4 += __shfl_xor_sync(0xffffffffu, a4, o);
            }
            if (lane < 4) {
                float* zA = &zsm[m*160 + wid*20 + gg];
                zA[ 0] = a0;
                zA[ 4] = a1;
                zA[ 8] = a2;
                zA[12] = a3;
                zA[16] = a4;
            }
        }
        __syncthreads();

        // ---- epilogue: 2 units per thread; push h pair to all 8 CTAs ----
        if (act) {
            float4 za = *(const float4*)&zsm[e_m*160 + e_ul*4];
            float4 zb = *(const float4*)&zsm[e_m*160 + e_ul*4 + 4];
            // unit e_ug
            float zi = za.x + pf[0][0];
            float zj = za.y + pf[1][0];
            float zf = za.z + pf[2][0];
            float zo = za.w + pf[3][0];
            float si = 1.f / (1.f + __expf(-zi));
            float sf = 1.f / (1.f + __expf(-(zf + 1.f)));  // FORGET_BIAS=1
            float so = 1.f / (1.f + __expf(-zo));
            float tj = tanhf(zj);
            c0 = c0 * sf + si * tj;
            float h0 = tanhf(c0) * so;
            // unit e_ug+1
            zi = zb.x + pf[0][1];
            zj = zb.y + pf[1][1];
            zf = zb.z + pf[2][1];
            zo = zb.w + pf[3][1];
            si = 1.f / (1.f + __expf(-zi));
            sf = 1.f / (1.f + __expf(-(zf + 1.f)));
            so = 1.f / (1.f + __expf(-zo));
            tj = tanhf(zj);
            c1 = c1 * sf + si * tj;
            float h1 = tanhf(c1) * so;

            if (t == e_len - 1) {   // final state for this row: single handoff
                float* hwr = g_h[(t & 1) ^ 1];
                __stcg(&hwr[e_b*HH + e_ug],     h0);
                __stcg(&hwr[e_b*HH + e_ug + 1], h1);
            }

            u64 hv2 = f2pack(h0, h1);
            unsigned off = poff + e_offb;
            #pragma unroll
            for (int r = 0; r < CL; r++)
                asm volatile("st.shared::cluster.b64 [%0], %1;"
                             :: "r"(rbase[r] + off), "l"(hv2) : "memory");
        }

        // ---- split barrier: arrive, prefetch next xz, then wait ----
        asm volatile("barrier.cluster.arrive.aligned;" ::: "memory");
        {
            const bool an = e_val && (t + 1 < e_len);
            const float* xp = e_xbase + (size_t)(t + 1)*NG;
            #pragma unroll
            for (int g = 0; g < 4; g++) {
                pf[g][0] = an ? __ldcg(xp + g*HH    ) : 0.f;
                pf[g][1] = an ? __ldcg(xp + g*HH + 1) : 0.f;
            }
        }
        asm volatile("barrier.cluster.wait.aligned;" ::: "memory");
    }
}

// ---------------------------------------------------------------------------
// final: logits + mean NLL. Row b's final h lives in buffer (lengths[b] & 1).
// ---------------------------------------------------------------------------
__global__ void final_kernel(
    const float* __restrict__ Wd,
    const float* __restrict__ bd,
    const int*   __restrict__ labels,
    const int*   __restrict__ lengths,
    float*       __restrict__ out,
    int out_size)
{
    __shared__ float red[128];
    __shared__ float wd_s[900];
    int b = threadIdx.x;
    for (int i = b; i < 900; i += 128) wd_s[i] = Wd[i];
    __syncthreads();

    const float* h = g_h[lengths[b] & 1] + b*HH;

    float a0 = bd[0], a1 = bd[1], a2 = bd[2];
    #pragma unroll 5
    for (int k = 0; k < HH; k += 4) {
        float4 hv = *(const float4*)(h + k);
        a0 += hv.x*wd_s[(k+0)*3+0] + hv.y*wd_s[(k+1)*3+0]
            + hv.z*wd_s[(k+2)*3+0] + hv.w*wd_s[(k+3)*3+0];
        a1 += hv.x*wd_s[(k+0)*3+1] + hv.y*wd_s[(k+1)*3+1]
            + hv.z*wd_s[(k+2)*3+1] + hv.w*wd_s[(k+3)*3+1];
        a2 += hv.x*wd_s[(k+0)*3+2] + hv.y*wd_s[(k+1)*3+2]
            + hv.z*wd_s[(k+2)*3+2] + hv.w*wd_s[(k+3)*3+2];
    }
    float mx  = fmaxf(a0, fmaxf(a1, a2));
    float lse = mx + logf(expf(a0 - mx) + expf(a1 - mx) + expf(a2 - mx));
    int   lab = labels[b];
    float sel = (lab == 0) ? a0 : ((lab == 1) ? a1 : a2);
    float nll = lse - sel;

    int off = (out_size >= 385) ? 1 : 0;
    if (out_size >= 384) {
        out[off + b*3 + 0] = a0;
        out[off + b*3 + 1] = a1;
        out[off + b*3 + 2] = a2;
    }
    red[b] = nll;
    __syncthreads();
    for (int s = 64; s; s >>= 1) {
        if (b < s) red[b] += red[b + s];
        __syncthreads();
    }
    if (b == 0 && (off == 1 || out_size < 384)) out[0] = red[0] * (1.f / 128.f);
}

// ---------------------------------------------------------------------------
extern "C" void kernel_launch(void* const* d_in, const int* in_sizes, int n_in,
                              void* d_out, int out_size)
{
    const int*   ids     = (const int*)  d_in[0];
    const int*   lengths = (const int*)  d_in[1];
    const int*   labels  = (const int*)  d_in[2];
    const float* emb     = (const float*)d_in[3];
    const float* W       = (const float*)d_in[4];
    const float* bl      = (const float*)d_in[5];
    const float* Wd      = (const float*)d_in[6];
    const float* bd      = (const float*)d_in[7];
    float* out = (float*)d_out;

    init_kernel<<<(BB*HH + 255)/256, 256>>>(lengths);
    precompute_kernel<<<dim3(19, 4, BB), 256>>>(ids, lengths, emb, W, bl);
    lstm_persistent<<<NCTAS, 256>>>(W, lengths);
    final_kernel<<<1, 128>>>(Wd, bd, labels, lengths, out, out_size);
}